// round 7
// baseline (speedup 1.0000x reference)
#include <cuda_runtime.h>
#include <math_constants.h>

#define B_ROWS 32768
#define C_COLS 1000
#define C_VEC4 250               // 1000 / 4
#define NCTA   592               // 4 resident CTAs per SM on 148 SMs
#define WPB    4                 // 128 threads
#define GWARPS (NCTA * WPB)      // 2368 persistent warps
#define FIXSCALE 4294967296.0    // 2^32

// Deterministic accumulator: integer atomics are exactly associative ->
// bit-identical result on every graph replay regardless of block order.
__device__ unsigned long long g_acc   = 0ULL;
__device__ unsigned int       g_count = 0u;

// Merge two descending sorted 4-lists -> top-4 of the union, descending, in a.
__device__ __forceinline__ void merge4(float& a0, float& a1, float& a2, float& a3,
                                       float b0, float b1, float b2, float b3) {
    float e0 = fmaxf(a0, b3);
    float e1 = fmaxf(a1, b2);
    float e2 = fmaxf(a2, b1);
    float e3 = fmaxf(a3, b0);
    float g0 = fmaxf(e0, e2), g2 = fminf(e0, e2);
    float g1 = fmaxf(e1, e3), g3 = fminf(e1, e3);
    a0 = fmaxf(g0, g1); a1 = fminf(g0, g1);
    a2 = fmaxf(g2, g3); a3 = fminf(g2, g3);
}

// Sort 4 arbitrary values descending: 5 comparators, depth 3.
__device__ __forceinline__ void sort4(float& x, float& y, float& z, float& w) {
    float s0 = fmaxf(x, y), s1 = fminf(x, y);
    float s2 = fmaxf(z, w), s3 = fminf(z, w);
    float m0 = fmaxf(s0, s2), m2 = fminf(s0, s2);
    float m1 = fmaxf(s1, s3), m3 = fminf(s1, s3);
    x = m0;
    y = fmaxf(m1, m2);
    z = fminf(m1, m2);
    w = m3;
}

__device__ __forceinline__ void load_row(const float* __restrict__ logits, int r,
                                         int lane, float4 (&v)[8]) {
    const float4* __restrict__ row =
        reinterpret_cast<const float4*>(logits + (size_t)r * C_COLS);
    #pragma unroll
    for (int it = 0; it < 8; ++it) {
        int i4 = it * 32 + lane;
        v[it] = __ldcs(&row[i4 < C_VEC4 ? i4 : (C_VEC4 - 1)]);  // clamp; masked below
    }
}

// Full per-row pipeline: lane scan -> butterfly reduce -> loss (same on all lanes).
__device__ __forceinline__ float process_row(float4 (&v)[8], int label, int lane) {
    float t0 = -CUDART_INF_F, t1 = -CUDART_INF_F, t2 = -CUDART_INF_F, t3 = -CUDART_INF_F;
    float lab = -CUDART_INF_F;
    #pragma unroll
    for (int it = 0; it < 8; ++it) {
        const int i4 = it * 32 + lane;
        const int base = i4 * 4;
        if (it == 7 && i4 >= C_VEC4) {          // tail lanes: kill clamped duplicate
            v[it].x = v[it].y = v[it].z = v[it].w = -CUDART_INF_F;
        }
        const unsigned d = (unsigned)(label - base);
        if (d < 4u) {                            // rare: this quad holds the label
            if      (d == 0u) { lab = v[it].x; v[it].x = -CUDART_INF_F; }
            else if (d == 1u) { lab = v[it].y; v[it].y = -CUDART_INF_F; }
            else if (d == 2u) { lab = v[it].z; v[it].z = -CUDART_INF_F; }
            else              { lab = v[it].w; v[it].w = -CUDART_INF_F; }
        }
        sort4(v[it].x, v[it].y, v[it].z, v[it].w);
        merge4(t0, t1, t2, t3, v[it].x, v[it].y, v[it].z, v[it].w);
    }
    // Butterfly: merge top-4 lists + label broadcast (5 shuffles/round, independent)
    #pragma unroll
    for (int off = 16; off; off >>= 1) {
        float s0 = __shfl_xor_sync(0xffffffffu, t0, off);
        float s1 = __shfl_xor_sync(0xffffffffu, t1, off);
        float s2 = __shfl_xor_sync(0xffffffffu, t2, off);
        float s3 = __shfl_xor_sync(0xffffffffu, t3, off);
        float sl = __shfl_xor_sync(0xffffffffu, lab, off);
        merge4(t0, t1, t2, t3, s0, s1, s2, s3);
        lab = fmaxf(lab, sl);
    }
    const float m = fmaxf(lab, t0);
    const float s = expf(lab - m) + expf(t0 - m) + expf(t1 - m)
                  + expf(t2 - m) + expf(t3 - m);
    return logf(s) + m - lab;                    // identical on all lanes
}

__global__ __launch_bounds__(128, 4)
void rowloss_kernel(const float* __restrict__ logits,
                    const int* __restrict__ labels32,
                    float* __restrict__ out) {
    const int gw   = (blockIdx.x * blockDim.x + threadIdx.x) >> 5;  // persistent warp id
    const int wib  = (threadIdx.x >> 5);
    const int lane = threadIdx.x & 31;

    // Label dtype probe: int64-LE with labels<1000 => all odd 32-bit words zero.
    const bool is64 = ((labels32[1] | labels32[3] | labels32[5] | labels32[7]) == 0);

    // ---- Software-pipelined grid-stride loop: while row r is in its ALU phase,
    // row r+GWARPS' loads (and label) are already in flight. Two fixed register
    // buffers (A, Bv) alternate; no indexed arrays -> no local memory.
    double acc = 0.0;
    float4 A[8], Bv[8];

    int r = gw;
    bool haveA = (r < B_ROWS);
    int  labA = 0;
    if (haveA) {
        labA = is64 ? labels32[2 * r] : labels32[r];
        load_row(logits, r, lane, A);
    }
    while (haveA) {
        const int r2 = r + GWARPS;
        const bool haveB = (r2 < B_ROWS);
        int labB = 0;
        if (haveB) {
            labB = is64 ? labels32[2 * r2] : labels32[r2];
            load_row(logits, r2, lane, Bv);          // prefetch next row
        }
        acc += (double)process_row(A, labA, lane);   // overlaps with Bv loads

        if (!haveB) break;
        const int r3 = r2 + GWARPS;
        haveA = (r3 < B_ROWS);
        if (haveA) {
            labA = is64 ? labels32[2 * r3] : labels32[r3];
            load_row(logits, r3, lane, A);           // prefetch next-next row
        }
        acc += (double)process_row(Bv, labB, lane);  // overlaps with A loads
        r = r3;
    }

    // Per-CTA deterministic partial -> one fixed-point atomic per CTA.
    __shared__ double sh_loss[WPB];
    if (lane == 0) sh_loss[wib] = acc;
    __syncthreads();

    if (threadIdx.x == 0) {
        double cta = 0.0;
        #pragma unroll
        for (int i = 0; i < WPB; ++i) cta += sh_loss[i];
        atomicAdd(&g_acc, (unsigned long long)(cta * FIXSCALE));
        __threadfence();
        const unsigned ticket = atomicAdd(&g_count, 1u);
        if (ticket == (unsigned)(NCTA - 1)) {        // last CTA: finalize + reset
            __threadfence();
            const unsigned long long total = atomicAdd(&g_acc, 0ULL);
            out[0] = (float)((double)total * (1.0 / FIXSCALE) * (1.0 / (double)B_ROWS));
            g_acc   = 0ULL;                          // replay-safe reset
            __threadfence();
            g_count = 0u;
        }
    }
}

extern "C" void kernel_launch(void* const* d_in, const int* in_sizes, int n_in,
                              void* d_out, int out_size) {
    const float* logits   = (const float*)d_in[0];
    const int*   labels32 = (const int*)d_in[1];   // dtype probed in-kernel
    float* out = (float*)d_out;

    rowloss_kernel<<<NCTA, 128>>>(logits, labels32, out);
}

// round 8
// speedup vs baseline: 1.0011x; 1.0011x over previous
#include <cuda_runtime.h>
#include <math_constants.h>

#define B_ROWS 32768
#define C_COLS 1000
#define C_VEC4 250               // 1000 / 4
#define NCTA   592               // 4 resident CTAs per SM on 148 SMs
#define WPB    4                 // 128 threads
#define GWARPS (NCTA * WPB)      // 2368 persistent warps
#define FIXSCALE 4294967296.0    // 2^32

// Deterministic accumulator: integer atomics are exactly associative ->
// bit-identical result on every graph replay regardless of block order.
__device__ unsigned long long g_acc   = 0ULL;
__device__ unsigned int       g_count = 0u;

// Merge two descending sorted 4-lists -> top-4 of the union, descending, in a.
__device__ __forceinline__ void merge4(float& a0, float& a1, float& a2, float& a3,
                                       float b0, float b1, float b2, float b3) {
    float e0 = fmaxf(a0, b3);
    float e1 = fmaxf(a1, b2);
    float e2 = fmaxf(a2, b1);
    float e3 = fmaxf(a3, b0);
    float g0 = fmaxf(e0, e2), g2 = fminf(e0, e2);
    float g1 = fmaxf(e1, e3), g3 = fminf(e1, e3);
    a0 = fmaxf(g0, g1); a1 = fminf(g0, g1);
    a2 = fmaxf(g2, g3); a3 = fminf(g2, g3);
}

// Sort 4 arbitrary values descending: 5 comparators, depth 3.
__device__ __forceinline__ void sort4(float& x, float& y, float& z, float& w) {
    float s0 = fmaxf(x, y), s1 = fminf(x, y);
    float s2 = fmaxf(z, w), s3 = fminf(z, w);
    float m0 = fmaxf(s0, s2), m2 = fminf(s0, s2);
    float m1 = fmaxf(s1, s3), m3 = fminf(s1, s3);
    x = m0;
    y = fmaxf(m1, m2);
    z = fminf(m1, m2);
    w = m3;
}

// DRAM->L2 prefetch of one full row (32 lanes x 128B lines covers 4000B).
// No dest register, no scoreboard: keeps DRAM busy independent of warp stalls.
__device__ __forceinline__ void prefetch_row(const float* __restrict__ logits,
                                             int r, int lane) {
    const char* p = reinterpret_cast<const char*>(logits + (size_t)r * C_COLS)
                  + lane * 128;
    asm volatile("prefetch.global.L2 [%0];" :: "l"(p));
}

__device__ __forceinline__ void load_row(const float* __restrict__ logits, int r,
                                         int lane, float4 (&v)[8]) {
    const float4* __restrict__ row =
        reinterpret_cast<const float4*>(logits + (size_t)r * C_COLS);
    #pragma unroll
    for (int it = 0; it < 8; ++it) {
        int i4 = it * 32 + lane;
        v[it] = __ldcs(&row[i4 < C_VEC4 ? i4 : (C_VEC4 - 1)]);  // clamp; masked below
    }
}

// Full per-row pipeline: lane scan -> butterfly reduce -> loss (same on all lanes).
__device__ __forceinline__ float process_row(float4 (&v)[8], int label, int lane) {
    float t0 = -CUDART_INF_F, t1 = -CUDART_INF_F, t2 = -CUDART_INF_F, t3 = -CUDART_INF_F;
    float lab = -CUDART_INF_F;
    #pragma unroll
    for (int it = 0; it < 8; ++it) {
        const int i4 = it * 32 + lane;
        const int base = i4 * 4;
        if (it == 7 && i4 >= C_VEC4) {          // tail lanes: kill clamped duplicate
            v[it].x = v[it].y = v[it].z = v[it].w = -CUDART_INF_F;
        }
        const unsigned d = (unsigned)(label - base);
        if (d < 4u) {                            // rare: this quad holds the label
            if      (d == 0u) { lab = v[it].x; v[it].x = -CUDART_INF_F; }
            else if (d == 1u) { lab = v[it].y; v[it].y = -CUDART_INF_F; }
            else if (d == 2u) { lab = v[it].z; v[it].z = -CUDART_INF_F; }
            else              { lab = v[it].w; v[it].w = -CUDART_INF_F; }
        }
        sort4(v[it].x, v[it].y, v[it].z, v[it].w);
        merge4(t0, t1, t2, t3, v[it].x, v[it].y, v[it].z, v[it].w);
    }
    // Butterfly: merge top-4 lists + label broadcast (5 shuffles/round, independent)
    #pragma unroll
    for (int off = 16; off; off >>= 1) {
        float s0 = __shfl_xor_sync(0xffffffffu, t0, off);
        float s1 = __shfl_xor_sync(0xffffffffu, t1, off);
        float s2 = __shfl_xor_sync(0xffffffffu, t2, off);
        float s3 = __shfl_xor_sync(0xffffffffu, t3, off);
        float sl = __shfl_xor_sync(0xffffffffu, lab, off);
        merge4(t0, t1, t2, t3, s0, s1, s2, s3);
        lab = fmaxf(lab, sl);
    }
    const float m = fmaxf(lab, t0);
    const float s = expf(lab - m) + expf(t0 - m) + expf(t1 - m)
                  + expf(t2 - m) + expf(t3 - m);
    return logf(s) + m - lab;                    // identical on all lanes
}

__global__ __launch_bounds__(128, 4)
void rowloss_kernel(const float* __restrict__ logits,
                    const int* __restrict__ labels32,
                    float* __restrict__ out) {
    const int gw   = (blockIdx.x * blockDim.x + threadIdx.x) >> 5;  // persistent warp id
    const int wib  = (threadIdx.x >> 5);
    const int lane = threadIdx.x & 31;

    // Label dtype probe: int64-LE with labels<1000 => all odd 32-bit words zero.
    const bool is64 = ((labels32[1] | labels32[3] | labels32[5] | labels32[7]) == 0);

    // ---- Software-pipelined grid-stride loop, one-stage register double-buffer,
    // plus an L2 prefetch running one further stage ahead.
    double acc = 0.0;
    float4 A[8], Bv[8];

    int r = gw;
    bool haveA = (r < B_ROWS);
    int  labA = 0;
    if (haveA) {
        prefetch_row(logits, (r + GWARPS < B_ROWS) ? r + GWARPS : r, lane);
        labA = is64 ? labels32[2 * r] : labels32[r];
        load_row(logits, r, lane, A);
    }
    while (haveA) {
        const int r2 = r + GWARPS;
        const bool haveB = (r2 < B_ROWS);
        int labB = 0;
        if (haveB) {
            prefetch_row(logits, (r2 + GWARPS < B_ROWS) ? r2 + GWARPS : r2, lane);
            labB = is64 ? labels32[2 * r2] : labels32[r2];
            load_row(logits, r2, lane, Bv);          // demand loads (mostly L2 hits)
        }
        acc += (double)process_row(A, labA, lane);   // overlaps with Bv loads

        if (!haveB) break;
        const int r3 = r2 + GWARPS;
        haveA = (r3 < B_ROWS);
        if (haveA) {
            prefetch_row(logits, (r3 + GWARPS < B_ROWS) ? r3 + GWARPS : r3, lane);
            labA = is64 ? labels32[2 * r3] : labels32[r3];
            load_row(logits, r3, lane, A);
        }
        acc += (double)process_row(Bv, labB, lane);  // overlaps with A loads
        r = r3;
    }

    // Per-CTA deterministic partial -> one fixed-point atomic per CTA.
    __shared__ double sh_loss[WPB];
    if (lane == 0) sh_loss[wib] = acc;
    __syncthreads();

    if (threadIdx.x == 0) {
        double cta = 0.0;
        #pragma unroll
        for (int i = 0; i < WPB; ++i) cta += sh_loss[i];
        atomicAdd(&g_acc, (unsigned long long)(cta * FIXSCALE));
        __threadfence();
        const unsigned ticket = atomicAdd(&g_count, 1u);
        if (ticket == (unsigned)(NCTA - 1)) {        // last CTA: finalize + reset
            __threadfence();
            const unsigned long long total = atomicAdd(&g_acc, 0ULL);
            out[0] = (float)((double)total * (1.0 / FIXSCALE) * (1.0 / (double)B_ROWS));
            g_acc   = 0ULL;                          // replay-safe reset
            __threadfence();
            g_count = 0u;
        }
    }
}

extern "C" void kernel_launch(void* const* d_in, const int* in_sizes, int n_in,
                              void* d_out, int out_size) {
    const float* logits   = (const float*)d_in[0];
    const int*   labels32 = (const int*)d_in[1];   // dtype probed in-kernel
    float* out = (float*)d_out;

    rowloss_kernel<<<NCTA, 128>>>(logits, labels32, out);
}